// round 5
// baseline (speedup 1.0000x reference)
#include <cuda_runtime.h>

#define B_ 8
#define C_ 3
#define T_ 32
#define H_ 256
#define W_ 256
#define NB 8
#define HB (H_ / NB)
#define WB (W_ / NB)
#define BLOCKS_PER_FRAME (HB * WB)   // 1024
#define TPB 128
#define MINBLK 6
#define CTAS_PER_FRAME (BLOCKS_PER_FRAME / TPB)  // 8

// 2*cos(k*pi/16)
#define A1 1.96157056080646f
#define A2 1.84775906502257f
#define A3 1.66293922460509f
#define A4 1.41421356237310f
#define A5 1.11114046603920f
#define A6 0.76536686473018f
#define A7 0.39018064403226f

// Unnormalized DCT-II, 8 points, even/odd butterfly.
__device__ __forceinline__ void dct8(const float i0, const float i1, const float i2,
                                     const float i3, const float i4, const float i5,
                                     const float i6, const float i7, float o[8]) {
    float s0 = i0 + i7, s1 = i1 + i6, s2 = i2 + i5, s3 = i3 + i4;
    float d0 = i0 - i7, d1 = i1 - i6, d2 = i2 - i5, d3 = i3 - i4;
    o[0] = 2.0f * ((s0 + s3) + (s1 + s2));
    o[4] = A4 * ((s0 + s3) - (s1 + s2));
    o[2] = A2 * s0 + A6 * s1 - A6 * s2 - A2 * s3;
    o[6] = A6 * s0 - A2 * s1 + A2 * s2 - A6 * s3;
    o[1] = A1 * d0 + A3 * d1 + A5 * d2 + A7 * d3;
    o[3] = A3 * d0 - A7 * d1 - A1 * d2 - A5 * d3;
    o[5] = A5 * d0 - A1 * d1 + A7 * d2 + A3 * d3;
    o[7] = A7 * d0 - A5 * d1 + A3 * d2 - A1 * d3;
}

__global__ __launch_bounds__(TPB, MINBLK)
void dct8x8_kernel(const float* __restrict__ x, float* __restrict__ out) {
    // 16B granules; XOR swizzle keeps STS.128 and LDS.128 conflict-free.
    __shared__ float4 stage[TPB * 16];   // 32 KB

    const int tid  = threadIdx.x;
    const int lane = tid & 31;
    const int warp = tid >> 5;
    const int cta_in_frame = blockIdx.x & (CTAS_PER_FRAME - 1);
    const int frame = blockIdx.x / CTAS_PER_FRAME;    // b*T + t
    const int b = frame >> 5;
    const int t = frame & 31;

    const int p  = cta_in_frame * TPB + tid;          // block index in frame
    const int hb = p >> 5;
    const int wb = p & 31;

    const long long chan_stride = (long long)T_ * H_ * W_;
    const float* base0 = x
        + (long long)b * C_ * chan_stride
        + (long long)t * H_ * W_
        + (long long)(hb * NB) * W_
        + (long long)(wb * NB);
    const float* base1 = base0 + chan_stride;
    const float* base2 = base1 + chan_stride;

    const float w0 = 0.2989f, w1 = 0.587f, w2 = 0.114f;

    // Load + gray reduce + row DCT (stage 1)
    float Y[8][8];
    #pragma unroll
    for (int r = 0; r < 8; ++r) {
        const int ro = r * W_;
        float4 a0 = *(const float4*)(base0 + ro);
        float4 a1 = *(const float4*)(base0 + ro + 4);
        float4 g0 = *(const float4*)(base1 + ro);
        float4 g1 = *(const float4*)(base1 + ro + 4);
        float4 c0 = *(const float4*)(base2 + ro);
        float4 c1 = *(const float4*)(base2 + ro + 4);
        float p0 = w0 * a0.x + w1 * g0.x + w2 * c0.x;
        float p1 = w0 * a0.y + w1 * g0.y + w2 * c0.y;
        float p2 = w0 * a0.z + w1 * g0.z + w2 * c0.z;
        float p3 = w0 * a0.w + w1 * g0.w + w2 * c0.w;
        float p4 = w0 * a1.x + w1 * g1.x + w2 * c1.x;
        float p5 = w0 * a1.y + w1 * g1.y + w2 * c1.y;
        float p6 = w0 * a1.z + w1 * g1.z + w2 * c1.z;
        float p7 = w0 * a1.w + w1 * g1.w + w2 * c1.w;
        dct8(p0, p1, p2, p3, p4, p5, p6, p7, Y[r]);
    }

    // Stage 2: column DCT
    float Z[8][8];
    #pragma unroll
    for (int l = 0; l < 8; ++l) {
        float col[8];
        dct8(Y[0][l], Y[1][l], Y[2][l], Y[3][l],
             Y[4][l], Y[5][l], Y[6][l], Y[7][l], col);
        #pragma unroll
        for (int k = 0; k < 8; ++k) Z[k][l] = col[k];
    }

    // Stage results into smem (swizzled), 16 granules of 16B per thread.
    const float4* zsrc = (const float4*)&Z[0][0];
    #pragma unroll
    for (int i = 0; i < 16; ++i) {
        stage[tid * 16 + (i ^ (tid & 15))] = zsrc[i];
    }
    __syncwarp();

    // Coalesced store: each warp writes its own 32 threads' 8KB contiguously.
    float4* out4 = (float4*)out
        + (long long)frame * (BLOCKS_PER_FRAME * 16)
        + (long long)cta_in_frame * (TPB * 16);
    #pragma unroll
    for (int c = 0; c < 16; ++c) {
        int m  = warp * 512 + c * 32 + lane;   // linear granule within CTA
        int tp = m >> 4;
        int j  = m & 15;
        float4 v = stage[tp * 16 + (j ^ (tp & 15))];
        __stcs(&out4[m], v);
    }
}

extern "C" void kernel_launch(void* const* d_in, const int* in_sizes, int n_in,
                              void* d_out, int out_size) {
    const float* x = (const float*)d_in[0];
    float* out = (float*)d_out;
    const int grid = B_ * T_ * CTAS_PER_FRAME;  // 2048
    dct8x8_kernel<<<grid, TPB>>>(x, out);
}

// round 7
// speedup vs baseline: 1.0842x; 1.0842x over previous
#include <cuda_runtime.h>

#define B_ 8
#define C_ 3
#define T_ 32
#define H_ 256
#define W_ 256
#define NB 8
#define HB (H_ / NB)
#define WB (W_ / NB)
#define BLOCKS_PER_FRAME (HB * WB)   // 1024
#define TPB 128
#define CTAS_PER_FRAME (BLOCKS_PER_FRAME / TPB)  // 8
#define TOTAL_WORK (B_ * T_ * CTAS_PER_FRAME)    // 2048
#define GRID 740                                  // 148 SMs * 5 CTAs/SM

// 2*cos(k*pi/16)
#define A1 1.96157056080646f
#define A2 1.84775906502257f
#define A3 1.66293922460509f
#define A4 1.41421356237310f
#define A5 1.11114046603920f
#define A6 0.76536686473018f
#define A7 0.39018064403226f

// Unnormalized DCT-II, 8 points, even/odd butterfly.
__device__ __forceinline__ void dct8(const float i0, const float i1, const float i2,
                                     const float i3, const float i4, const float i5,
                                     const float i6, const float i7, float o[8]) {
    float s0 = i0 + i7, s1 = i1 + i6, s2 = i2 + i5, s3 = i3 + i4;
    float d0 = i0 - i7, d1 = i1 - i6, d2 = i2 - i5, d3 = i3 - i4;
    o[0] = 2.0f * ((s0 + s3) + (s1 + s2));
    o[4] = A4 * ((s0 + s3) - (s1 + s2));
    o[2] = A2 * s0 + A6 * s1 - A6 * s2 - A2 * s3;
    o[6] = A6 * s0 - A2 * s1 + A2 * s2 - A6 * s3;
    o[1] = A1 * d0 + A3 * d1 + A5 * d2 + A7 * d3;
    o[3] = A3 * d0 - A7 * d1 - A1 * d2 - A5 * d3;
    o[5] = A5 * d0 - A1 * d1 + A7 * d2 + A3 * d3;
    o[7] = A7 * d0 - A5 * d1 + A3 * d2 - A1 * d3;
}

__global__ __launch_bounds__(TPB)
void dct8x8_kernel(const float* __restrict__ x, float* __restrict__ out) {
    // 16B granules; XOR swizzle keeps STS.128 and LDS.128 conflict-free.
    // Warp-private regions -> __syncwarp only.
    __shared__ float4 stage[TPB * 16];   // 32 KB

    const int tid  = threadIdx.x;
    const int lane = tid & 31;
    const int warp = tid >> 5;
    const long long chan_stride = (long long)T_ * H_ * W_;
    const float w0 = 0.2989f, w1 = 0.587f, w2 = 0.114f;

    for (int work = blockIdx.x; work < TOTAL_WORK; work += GRID) {
        const int cta_in_frame = work & (CTAS_PER_FRAME - 1);
        const int frame = work >> 3;                  // b*T + t
        const int b = frame >> 5;
        const int t = frame & 31;

        const int p  = cta_in_frame * TPB + tid;      // block index in frame
        const int hb = p >> 5;
        const int wb = p & 31;

        const float* base0 = x
            + (long long)b * C_ * chan_stride
            + (long long)t * H_ * W_
            + (long long)(hb * NB) * W_
            + (long long)(wb * NB);
        const float* base1 = base0 + chan_stride;
        const float* base2 = base1 + chan_stride;

        // Load + gray reduce + row DCT (stage 1)
        float Y[8][8];
        #pragma unroll
        for (int r = 0; r < 8; ++r) {
            const int ro = r * W_;
            float4 a0 = *(const float4*)(base0 + ro);
            float4 a1 = *(const float4*)(base0 + ro + 4);
            float4 g0 = *(const float4*)(base1 + ro);
            float4 g1 = *(const float4*)(base1 + ro + 4);
            float4 c0 = *(const float4*)(base2 + ro);
            float4 c1 = *(const float4*)(base2 + ro + 4);
            float p0 = w0 * a0.x + w1 * g0.x + w2 * c0.x;
            float p1 = w0 * a0.y + w1 * g0.y + w2 * c0.y;
            float p2 = w0 * a0.z + w1 * g0.z + w2 * c0.z;
            float p3 = w0 * a0.w + w1 * g0.w + w2 * c0.w;
            float p4 = w0 * a1.x + w1 * g1.x + w2 * c1.x;
            float p5 = w0 * a1.y + w1 * g1.y + w2 * c1.y;
            float p6 = w0 * a1.z + w1 * g1.z + w2 * c1.z;
            float p7 = w0 * a1.w + w1 * g1.w + w2 * c1.w;
            dct8(p0, p1, p2, p3, p4, p5, p6, p7, Y[r]);
        }

        // Stage 2: column DCT
        float Z[8][8];
        #pragma unroll
        for (int l = 0; l < 8; ++l) {
            float col[8];
            dct8(Y[0][l], Y[1][l], Y[2][l], Y[3][l],
                 Y[4][l], Y[5][l], Y[6][l], Y[7][l], col);
            #pragma unroll
            for (int k = 0; k < 8; ++k) Z[k][l] = col[k];
        }

        // Stage results into smem (swizzled), 16 granules of 16B per thread.
        const float4* zsrc = (const float4*)&Z[0][0];
        #pragma unroll
        for (int i = 0; i < 16; ++i) {
            stage[tid * 16 + (i ^ (tid & 15))] = zsrc[i];
        }
        __syncwarp();

        // Coalesced store: each warp writes its own 32 threads' 8KB contiguously.
        float4* out4 = (float4*)out
            + (long long)frame * (BLOCKS_PER_FRAME * 16)
            + (long long)cta_in_frame * (TPB * 16);
        #pragma unroll
        for (int c = 0; c < 16; ++c) {
            int m  = warp * 512 + c * 32 + lane;   // linear granule within CTA
            int tp = m >> 4;
            int j  = m & 15;
            float4 v = stage[tp * 16 + (j ^ (tp & 15))];
            __stcs(&out4[m], v);
        }
        __syncwarp();
    }
}

extern "C" void kernel_launch(void* const* d_in, const int* in_sizes, int n_in,
                              void* d_out, int out_size) {
    const float* x = (const float*)d_in[0];
    float* out = (float*)d_out;
    dct8x8_kernel<<<GRID, TPB>>>(x, out);
}

// round 8
// speedup vs baseline: 1.2303x; 1.1348x over previous
#include <cuda_runtime.h>

#define B_ 8
#define C_ 3
#define T_ 32
#define H_ 256
#define W_ 256
#define NB 8
#define HB (H_ / NB)
#define WB (W_ / NB)
#define BLOCKS_PER_FRAME (HB * WB)   // 1024
#define TPB 128
#define CTAS_PER_FRAME (BLOCKS_PER_FRAME / TPB)  // 8

// 2*cos(k*pi/16)
#define A1 1.96157056080646f
#define A2 1.84775906502257f
#define A3 1.66293922460509f
#define A4 1.41421356237310f
#define A5 1.11114046603920f
#define A6 0.76536686473018f
#define A7 0.39018064403226f

// Unnormalized DCT-II, 8 points, even/odd butterfly.
__device__ __forceinline__ void dct8(const float i0, const float i1, const float i2,
                                     const float i3, const float i4, const float i5,
                                     const float i6, const float i7, float o[8]) {
    float s0 = i0 + i7, s1 = i1 + i6, s2 = i2 + i5, s3 = i3 + i4;
    float d0 = i0 - i7, d1 = i1 - i6, d2 = i2 - i5, d3 = i3 - i4;
    o[0] = 2.0f * ((s0 + s3) + (s1 + s2));
    o[4] = A4 * ((s0 + s3) - (s1 + s2));
    o[2] = A2 * s0 + A6 * s1 - A6 * s2 - A2 * s3;
    o[6] = A6 * s0 - A2 * s1 + A2 * s2 - A6 * s3;
    o[1] = A1 * d0 + A3 * d1 + A5 * d2 + A7 * d3;
    o[3] = A3 * d0 - A7 * d1 - A1 * d2 - A5 * d3;
    o[5] = A5 * d0 - A1 * d1 + A7 * d2 + A3 * d3;
    o[7] = A7 * d0 - A5 * d1 + A3 * d2 - A1 * d3;
}

__global__ __launch_bounds__(TPB)
void dct8x8_kernel(const float* __restrict__ x, float* __restrict__ out) {
    // 16B granules; XOR swizzle keeps STS.128 and LDS.128 conflict-free.
    __shared__ float4 stage[TPB * 16];   // 32 KB

    const int tid  = threadIdx.x;
    const int lane = tid & 31;
    const int warp = tid >> 5;
    const int cta_in_frame = blockIdx.x & (CTAS_PER_FRAME - 1);
    const int frame = blockIdx.x / CTAS_PER_FRAME;    // b*T + t
    const int b = frame >> 5;
    const int t = frame & 31;

    const int p  = cta_in_frame * TPB + tid;          // block index in frame
    const int hb = p >> 5;
    const int wb = p & 31;

    const long long chan_stride = (long long)T_ * H_ * W_;
    const float* base0 = x
        + (long long)b * C_ * chan_stride
        + (long long)t * H_ * W_
        + (long long)(hb * NB) * W_
        + (long long)(wb * NB);
    const float* base1 = base0 + chan_stride;
    const float* base2 = base1 + chan_stride;

    const float w0 = 0.2989f, w1 = 0.587f, w2 = 0.114f;

    // Software-pipelined: loads for row r+1 issue before math for row r.
    float Y[8][8];
    float4 a0 = *(const float4*)(base0);
    float4 a1 = *(const float4*)(base0 + 4);
    float4 g0 = *(const float4*)(base1);
    float4 g1 = *(const float4*)(base1 + 4);
    float4 c0 = *(const float4*)(base2);
    float4 c1 = *(const float4*)(base2 + 4);
    #pragma unroll
    for (int r = 0; r < 8; ++r) {
        float4 na0, na1, ng0, ng1, nc0, nc1;
        if (r < 7) {
            const int ro = (r + 1) * W_;
            na0 = *(const float4*)(base0 + ro);
            na1 = *(const float4*)(base0 + ro + 4);
            ng0 = *(const float4*)(base1 + ro);
            ng1 = *(const float4*)(base1 + ro + 4);
            nc0 = *(const float4*)(base2 + ro);
            nc1 = *(const float4*)(base2 + ro + 4);
        }
        float p0 = w0 * a0.x + w1 * g0.x + w2 * c0.x;
        float p1 = w0 * a0.y + w1 * g0.y + w2 * c0.y;
        float p2 = w0 * a0.z + w1 * g0.z + w2 * c0.z;
        float p3 = w0 * a0.w + w1 * g0.w + w2 * c0.w;
        float p4 = w0 * a1.x + w1 * g1.x + w2 * c1.x;
        float p5 = w0 * a1.y + w1 * g1.y + w2 * c1.y;
        float p6 = w0 * a1.z + w1 * g1.z + w2 * c1.z;
        float p7 = w0 * a1.w + w1 * g1.w + w2 * c1.w;
        dct8(p0, p1, p2, p3, p4, p5, p6, p7, Y[r]);
        if (r < 7) {
            a0 = na0; a1 = na1; g0 = ng0; g1 = ng1; c0 = nc0; c1 = nc1;
        }
    }

    // Stage 2: column DCT
    float Z[8][8];
    #pragma unroll
    for (int l = 0; l < 8; ++l) {
        float col[8];
        dct8(Y[0][l], Y[1][l], Y[2][l], Y[3][l],
             Y[4][l], Y[5][l], Y[6][l], Y[7][l], col);
        #pragma unroll
        for (int k = 0; k < 8; ++k) Z[k][l] = col[k];
    }

    // Stage results into smem (swizzled), 16 granules of 16B per thread.
    const float4* zsrc = (const float4*)&Z[0][0];
    #pragma unroll
    for (int i = 0; i < 16; ++i) {
        stage[tid * 16 + (i ^ (tid & 15))] = zsrc[i];
    }
    __syncwarp();

    // Coalesced store: each warp writes its own 32 threads' 8KB contiguously.
    float4* out4 = (float4*)out
        + (long long)frame * (BLOCKS_PER_FRAME * 16)
        + (long long)cta_in_frame * (TPB * 16);
    #pragma unroll
    for (int c = 0; c < 16; ++c) {
        int m  = warp * 512 + c * 32 + lane;   // linear granule within CTA
        int tp = m >> 4;
        int j  = m & 15;
        float4 v = stage[tp * 16 + (j ^ (tp & 15))];
        __stcs(&out4[m], v);
    }
}

extern "C" void kernel_launch(void* const* d_in, const int* in_sizes, int n_in,
                              void* d_out, int out_size) {
    const float* x = (const float*)d_in[0];
    float* out = (float*)d_out;
    const int grid = B_ * T_ * CTAS_PER_FRAME;  // 2048
    dct8x8_kernel<<<grid, TPB>>>(x, out);
}